// round 8
// baseline (speedup 1.0000x reference)
#include <cuda_runtime.h>
#include <cuda_fp16.h>
#include <cstdint>

#define B_ 16
#define S_ 2048
#define H_ 512
#define W_ 4
#define L_ 2
#define SP_ (S_ + 2 * W_)   // 2056
#define BS_ (B_ * S_)       // 32768

// ---------------------------------------------------------------------------
// Scratch (__device__ globals; allocation-free rule)
// ---------------------------------------------------------------------------
__device__ __align__(256) __half g_pad_h[B_ * SP_ * H_];     // fp16 padded input
__device__ __align__(256) float  g_lo[BS_ * H_];             // fp32 residual L
__device__ __align__(256) float  g_ro[BS_ * H_];             // fp32 residual R
__device__ __align__(256) __half g_u[2 * BS_ * H_];          // fp16 x*gamma (GEMM1 A), per side
__device__ __align__(256) __half g_h[2 * BS_ * H_];          // fp16 hidden (GEMM2 A), per side
__device__ __align__(256) float  g_stats[4 * BS_ * 2];       // (sum, sumsq) x 4 phases
__device__ __align__(256) float  g_q[4 * H_];                // gamma @ W1 per (layer,side)
__device__ __align__(256) float  g_p[4 * H_];                // beta @ W1 + b1
// fp16 weights, layout matches f2h_all linear order:
#define OFF_WL  0
#define OFF_WR  1048576
#define OFF_LW1 2097152
#define OFF_LW2 2621440
#define OFF_RW1 3145728
#define OFF_RW2 3670016
__device__ __align__(256) __half g_wh[4194304];

// ---------------------------------------------------------------------------
// PTX helpers
// ---------------------------------------------------------------------------
__device__ __forceinline__ uint32_t smem_u32(const void* p) {
    uint32_t a;
    asm("{ .reg .u64 t; cvta.to.shared.u64 t, %1; cvt.u32.u64 %0, t; }" : "=r"(a) : "l"(p));
    return a;
}
__device__ __forceinline__ void cp_async16(uint32_t dst, const void* src) {
    asm volatile("cp.async.cg.shared.global [%0], [%1], 16;" :: "r"(dst), "l"(src) : "memory");
}
template <int N>
__device__ __forceinline__ void cp_wait() {
    asm volatile("cp.async.wait_group %0;" :: "n"(N) : "memory");
}
#define CP_COMMIT() asm volatile("cp.async.commit_group;" ::: "memory")

__device__ __forceinline__ void ldm_x4(uint32_t r[4], uint32_t addr) {
    asm volatile("ldmatrix.sync.aligned.m8n8.x4.shared.b16 {%0,%1,%2,%3}, [%4];"
        : "=r"(r[0]), "=r"(r[1]), "=r"(r[2]), "=r"(r[3]) : "r"(addr));
}
__device__ __forceinline__ void ldm_x4_t(uint32_t r[4], uint32_t addr) {
    asm volatile("ldmatrix.sync.aligned.m8n8.x4.trans.shared.b16 {%0,%1,%2,%3}, [%4];"
        : "=r"(r[0]), "=r"(r[1]), "=r"(r[2]), "=r"(r[3]) : "r"(addr));
}
__device__ __forceinline__ void mma_f16(float c[4], const uint32_t a[4],
                                        uint32_t b0, uint32_t b1) {
    asm volatile(
        "mma.sync.aligned.m16n8k16.row.col.f32.f16.f16.f32 "
        "{%0,%1,%2,%3}, {%4,%5,%6,%7}, {%8,%9}, {%0,%1,%2,%3};"
        : "+f"(c[0]), "+f"(c[1]), "+f"(c[2]), "+f"(c[3])
        : "r"(a[0]), "r"(a[1]), "r"(a[2]), "r"(a[3]), "r"(b0), "r"(b1));
}

// ---------------------------------------------------------------------------
// Single kernel: convert ALL fp32 weights -> fp16 into g_wh (linear layout)
// ---------------------------------------------------------------------------
__global__ void f2h_all(const float* __restrict__ Wl, const float* __restrict__ Wr,
                        const float* __restrict__ lw1, const float* __restrict__ lw2,
                        const float* __restrict__ rw1, const float* __restrict__ rw2) {
    int i = blockIdx.x * blockDim.x + threadIdx.x;   // uint4 index (8 halves)
    if (i >= 524288) return;
    const float* src;
    int off;
    if (i < 131072)      { src = Wl;  off = i; }
    else if (i < 262144) { src = Wr;  off = i - 131072; }
    else if (i < 327680) { src = lw1; off = i - 262144; }
    else if (i < 393216) { src = lw2; off = i - 327680; }
    else if (i < 458752) { src = rw1; off = i - 393216; }
    else                 { src = rw2; off = i - 458752; }
    float4 v0 = ((const float4*)src)[2 * off];
    float4 v1 = ((const float4*)src)[2 * off + 1];
    __half2 h[4];
    h[0] = __floats2half2_rn(v0.x, v0.y);
    h[1] = __floats2half2_rn(v0.z, v0.w);
    h[2] = __floats2half2_rn(v1.x, v1.y);
    h[3] = __floats2half2_rn(v1.z, v1.w);
    ((uint4*)g_wh)[i] = *(uint4*)h;
}

// ---------------------------------------------------------------------------
// prep: q = gamma @ W1, p = beta @ W1 + b1, per combo = layer*2 + side
// ---------------------------------------------------------------------------
__global__ void prep_qp(const float* __restrict__ lw1, const float* __restrict__ rw1,
                        const float* __restrict__ lg, const float* __restrict__ lbeta,
                        const float* __restrict__ lb1,
                        const float* __restrict__ rg, const float* __restrict__ rbeta,
                        const float* __restrict__ rb1) {
    int combo = blockIdx.y;
    int layer = combo >> 1, side = combo & 1;
    const float* Wm = (side ? rw1 : lw1) + (size_t)layer * H_ * H_;
    const float* ga = (side ? rg : lg) + layer * H_;
    const float* be = (side ? rbeta : lbeta) + layer * H_;
    const float* b1 = (side ? rb1 : lb1) + layer * H_;
    int j = blockIdx.x * 128 + threadIdx.x;
    float q = 0.f, p = 0.f;
    for (int k = 0; k < H_; k++) {
        float w = Wm[(size_t)k * H_ + j];
        q += ga[k] * w;
        p += be[k] * w;
    }
    g_q[combo * H_ + j] = q;
    g_p[combo * H_ + j] = p + b1[j];
}

// ---------------------------------------------------------------------------
// pad: [left ; inputs ; right] -> g_pad_h (fp16)
// ---------------------------------------------------------------------------
__global__ void pad_kernel(const float* __restrict__ inp,
                           const float* __restrict__ lp,
                           const float* __restrict__ rp) {
    const int H4 = H_ / 4;
    int idx = blockIdx.x * blockDim.x + threadIdx.x;
    if (idx >= B_ * SP_ * H4) return;
    int h4 = idx % H4;
    int t = idx / H4;
    int p = t % SP_;
    int b = t / SP_;
    float4 v;
    if (p < W_) v = ((const float4*)lp)[p * H4 + h4];
    else if (p < W_ + S_) v = ((const float4*)inp)[((size_t)b * S_ + (p - W_)) * H4 + h4];
    else v = ((const float4*)rp)[(p - W_ - S_) * H4 + h4];
    __half2 h[2];
    h[0] = __floats2half2_rn(v.x, v.y);
    h[1] = __floats2half2_rn(v.z, v.w);
    ((uint2*)g_pad_h)[idx] = *(uint2*)h;
}

// ---------------------------------------------------------------------------
// fp16 mma.sync GEMM: 128x128 CTA tile, 128 threads = 4 warps (2x2),
// warp tile 64x64 (halves cross-warp smem fragment redundancy vs 2x4/64x32).
// BK=32, 4-stage cp.async, single __syncthreads per chunk.
// MODE 0 (grid 4,16,32): wide proj. Epilogue: relu(acc+b) -> X fp32,
//        u = fp16(v*gamma0), atomic stats phase side.
// MODE 1 (grid 4,256,2): A = g_u[side]. v = rstd*acc - rstd*mu*q + p, relu
//        -> g_h[side] fp16.
// MODE 2 (grid 4,256,2): A = g_h[side]. v = X + acc + b2 -> out_all (+out_last)
//        at column side*H_. If not last: X = v, u, stats phase 2+side.
// ---------------------------------------------------------------------------
constexpr int A_STAGE_B = 128 * 80;
constexpr int B_STAGE_B = 32 * 272;
constexpr int STAGE_B = A_STAGE_B + B_STAGE_B;  // 18944 B
constexpr int STAGES = 4;
constexpr int SMEM_BYTES = STAGES * STAGE_B;    // 75776 B (2 CTAs/SM)

template <int MODE, int KT>
__global__ void __launch_bounds__(128, 2)
tc_gemm(int woffL, int woffR,
        const float* __restrict__ bL, const float* __restrict__ bR,
        const float* __restrict__ gamL, const float* __restrict__ gamR,
        int qp_base, int statsPhase, int ln_phase,
        float* __restrict__ outA, float* __restrict__ outL) {
    extern __shared__ char smraw[];
    const uint32_t sbase = smem_u32(smraw);
    const int tid = threadIdx.x;
    const int lane = tid & 31, wid = tid >> 5;
    const int warpM = wid >> 1, warpN = wid & 1;   // 2x2 grid, 64x64 warp tile
    const int gid = lane >> 2, t4 = lane & 3;
    const int lane15 = lane & 15, laneHi = lane >> 4;
    const int n0 = blockIdx.x * 128;

    int side;
    size_t m0;
    const __half* A;
    if (MODE == 0) {
        side = blockIdx.z >> 4;
        int bb = blockIdx.z & 15;
        m0 = (size_t)bb * S_ + blockIdx.y * 128;
        A = g_pad_h + ((size_t)bb * SP_ + blockIdx.y * 128 + side * (W_ + 1)) * H_;
    } else {
        side = blockIdx.z;
        m0 = (size_t)blockIdx.y * 128;
        A = (MODE == 1 ? g_u : g_h) + ((size_t)side * BS_ + m0) * H_;
    }
    const __half* Wm = g_wh + (side ? woffR : woffL);
    float* X = side ? g_ro : g_lo;
    const float* bias = side ? bR : bL;
    const float* gam = side ? gamR : gamL;

    float c[4][8][4];   // mr (4x16 rows) x nr (8x8 cols) x quad
#pragma unroll
    for (int i = 0; i < 4; i++)
#pragma unroll
        for (int j = 0; j < 8; j++)
#pragma unroll
            for (int q = 0; q < 4; q++) c[i][j][q] = 0.f;

    auto loadStage = [&](int kt, int s) {
        const int k0 = kt * 32;
        uint32_t base = sbase + (uint32_t)s * STAGE_B;
#pragma unroll
        for (int i = 0; i < 4; i++) {
            int ch = tid + i * 128;
            int ar = ch >> 2, ac = ch & 3;
            cp_async16(base + ar * 80 + ac * 16, A + (size_t)ar * H_ + k0 + ac * 8);
            int br = ch >> 4, bc = ch & 15;
            cp_async16(base + A_STAGE_B + br * 272 + bc * 16,
                       Wm + (size_t)(k0 + br) * H_ + n0 + bc * 8);
        }
        CP_COMMIT();
    };

    // prologue: fill 3 of 4 stages
    loadStage(0, 0);
    if (KT > 1) loadStage(1, 1);
    if (KT > 2) loadStage(2, 2);

    for (int kt = 0; kt < KT; kt++) {
        int rem = KT - 1 - kt;
        if (rem >= 2) cp_wait<2>();
        else if (rem == 1) cp_wait<1>();
        else cp_wait<0>();
        __syncthreads();
        if (kt + 3 < KT) loadStage(kt + 3, (kt + 3) % STAGES);

        const uint32_t a_base = sbase + (uint32_t)((kt % STAGES) * STAGE_B);
        const uint32_t b_base = a_base + A_STAGE_B;
#pragma unroll
        for (int ks = 0; ks < 2; ks++) {
            uint32_t a[4][4], bb2[4][4];
#pragma unroll
            for (int mr = 0; mr < 4; mr++)
                ldm_x4(a[mr], a_base + (warpM * 64 + mr * 16 + lane15) * 80
                                 + ks * 32 + laneHi * 16);
#pragma unroll
            for (int np = 0; np < 4; np++)
                ldm_x4_t(bb2[np], b_base + (ks * 16 + lane15) * 272
                                    + (warpN * 64 + np * 16 + laneHi * 8) * 2);
#pragma unroll
            for (int mr = 0; mr < 4; mr++)
#pragma unroll
                for (int np = 0; np < 4; np++) {
                    mma_f16(c[mr][2 * np + 0], a[mr], bb2[np][0], bb2[np][1]);
                    mma_f16(c[mr][2 * np + 1], a[mr], bb2[np][2], bb2[np][3]);
                }
        }
    }

    // ---------------- epilogue ----------------
    const int colbase = n0 + warpN * 64 + t4 * 2;
    __half* uSide = g_u + (size_t)side * BS_ * H_;

    if (MODE == 1) {
        const int cb = (qp_base + side) * H_;
        const float* stats = g_stats + (size_t)(ln_phase + side) * BS_ * 2;
        __half* hSide = g_h + (size_t)side * BS_ * H_;
#pragma unroll
        for (int mr = 0; mr < 4; mr++) {
#pragma unroll
            for (int hh = 0; hh < 2; hh++) {
                size_t r = m0 + warpM * 64 + mr * 16 + gid + hh * 8;
                float2 st = *(const float2*)(stats + r * 2);
                float mu = st.x * (1.0f / H_);
                float var = st.y * (1.0f / H_) - mu * mu;
                float rstd = rsqrtf(fmaxf(var, 0.f) + 1e-5f);
                float mt = -rstd * mu;
                __half* hrow = hSide + r * H_;
#pragma unroll
                for (int nr = 0; nr < 8; nr++) {
                    int col = colbase + nr * 8;
                    float2 q2 = *(const float2*)(g_q + cb + col);
                    float2 p2 = *(const float2*)(g_p + cb + col);
                    float v0 = fmaf(rstd, c[mr][nr][hh * 2 + 0], fmaf(mt, q2.x, p2.x));
                    float v1 = fmaf(rstd, c[mr][nr][hh * 2 + 1], fmaf(mt, q2.y, p2.y));
                    *(__half2*)(hrow + col) =
                        __floats2half2_rn(fmaxf(v0, 0.f), fmaxf(v1, 0.f));
                }
            }
        }
        return;
    }

    // MODE 0 / MODE 2
    float* statsDst = (statsPhase >= 0)
        ? g_stats + (size_t)(statsPhase + side) * BS_ * 2 : (float*)0;
    const int outcol0 = colbase + side * H_;   // concat offset in [.,.,2H] outputs

#pragma unroll
    for (int mr = 0; mr < 4; mr++) {
#pragma unroll
        for (int hh = 0; hh < 2; hh++) {
            size_t r = m0 + warpM * 64 + mr * 16 + gid + hh * 8;
            float* xrow = X + r * H_;
            float s = 0.f, sq = 0.f;
#pragma unroll
            for (int nr = 0; nr < 8; nr++) {
                int col = colbase + nr * 8;
                float2 bv = *(const float2*)(bias + col);
                float v0 = c[mr][nr][hh * 2 + 0] + bv.x;
                float v1 = c[mr][nr][hh * 2 + 1] + bv.y;
                if (MODE == 0) {
                    v0 = fmaxf(v0, 0.f);
                    v1 = fmaxf(v1, 0.f);
                    *(float2*)(xrow + col) = make_float2(v0, v1);
                } else {
                    float2 rv = *(const float2*)(xrow + col);
                    v0 += rv.x;
                    v1 += rv.y;
                    size_t bi = r >> 11, si = r & 2047;
                    int ocol = outcol0 + nr * 8;
                    *(float2*)(outA + (si * B_ + bi) * (size_t)(2 * H_) + ocol) =
                        make_float2(v0, v1);
                    if (outL)
                        *(float2*)(outL + (bi * S_ + si) * (size_t)(2 * H_) + ocol) =
                            make_float2(v0, v1);
                    if (statsPhase >= 0) *(float2*)(xrow + col) = make_float2(v0, v1);
                }
                if (MODE == 0 || statsPhase >= 0) {
                    float2 gv = *(const float2*)(gam + col);
                    *(__half2*)(uSide + r * H_ + col) =
                        __floats2half2_rn(v0 * gv.x, v1 * gv.y);
                    s += v0 + v1;
                    sq += v0 * v0 + v1 * v1;
                }
            }
            if (statsDst) {
                s += __shfl_xor_sync(0xffffffffu, s, 1);
                sq += __shfl_xor_sync(0xffffffffu, sq, 1);
                s += __shfl_xor_sync(0xffffffffu, s, 2);
                sq += __shfl_xor_sync(0xffffffffu, sq, 2);
                if (t4 == 0) {
                    atomicAdd(statsDst + r * 2, s);
                    atomicAdd(statsDst + r * 2 + 1, sq);
                }
            }
        }
    }
}

// ---------------------------------------------------------------------------
extern "C" void kernel_launch(void* const* d_in, const int* in_sizes, int n_in,
                              void* d_out, int out_size) {
    const float* inputs = (const float*)d_in[0];
    const float* lp     = (const float*)d_in[1];
    const float* rp     = (const float*)d_in[2];
    const float* Wl     = (const float*)d_in[3];
    const float* bl     = (const float*)d_in[4];
    const float* Wr     = (const float*)d_in[5];
    const float* br     = (const float*)d_in[6];
    const float* lw1    = (const float*)d_in[7];
    const float* lb1    = (const float*)d_in[8];
    const float* lw2    = (const float*)d_in[9];
    const float* lb2    = (const float*)d_in[10];
    const float* lg     = (const float*)d_in[11];
    const float* lbeta  = (const float*)d_in[12];
    const float* rw1    = (const float*)d_in[13];
    const float* rb1    = (const float*)d_in[14];
    const float* rw2    = (const float*)d_in[15];
    const float* rb2    = (const float*)d_in[16];
    const float* rg     = (const float*)d_in[17];
    const float* rbeta  = (const float*)d_in[18];
    float* out = (float*)d_out;
    (void)in_sizes; (void)n_in; (void)out_size;

    cudaFuncSetAttribute(tc_gemm<0, 64>, cudaFuncAttributeMaxDynamicSharedMemorySize, SMEM_BYTES);
    cudaFuncSetAttribute(tc_gemm<1, 16>, cudaFuncAttributeMaxDynamicSharedMemorySize, SMEM_BYTES);
    cudaFuncSetAttribute(tc_gemm<2, 16>, cudaFuncAttributeMaxDynamicSharedMemorySize, SMEM_BYTES);

    // 0) zero stats
    float* statsPtr;
    cudaGetSymbolAddress((void**)&statsPtr, g_stats);
    cudaMemsetAsync(statsPtr, 0, 4 * BS_ * 2 * sizeof(float));

    // 1) pad + weight convert + LN-fold precompute
    int padTotal = B_ * SP_ * (H_ / 4);
    pad_kernel<<<(padTotal + 255) / 256, 256>>>(inputs, lp, rp);
    f2h_all<<<2048, 256>>>(Wl, Wr, lw1, lw2, rw1, rw2);
    prep_qp<<<dim3(4, 4), 128>>>(lw1, rw1, lg, lbeta, lb1, rg, rbeta, rb1);

    // 2) wide projections, L+R merged (stats phase 0/1, u with layer-0 gamma)
    tc_gemm<0, 64><<<dim3(4, 16, 32), 128, SMEM_BYTES>>>(
        OFF_WL, OFF_WR, bl, br, lg, rg, 0, 0, 0, nullptr, nullptr);

    // 3) residual FF layers, L+R merged per launch
    for (int i = 0; i < L_; i++) {
        bool last = (i == L_ - 1);
        tc_gemm<1, 16><<<dim3(4, 256, 2), 128, SMEM_BYTES>>>(
            OFF_LW1 + i * 262144, OFF_RW1 + i * 262144,
            nullptr, nullptr, nullptr, nullptr,
            i * 2, -1, (i == 0) ? 0 : 2, nullptr, nullptr);

        float* oall = out + (size_t)i * S_ * B_ * 2 * H_;
        float* olast = last ? out + (size_t)L_ * S_ * B_ * 2 * H_ : nullptr;
        tc_gemm<2, 16><<<dim3(4, 256, 2), 128, SMEM_BYTES>>>(
            OFF_LW2 + i * 262144, OFF_RW2 + i * 262144,
            lb2 + (size_t)i * H_, rb2 + (size_t)i * H_,
            last ? nullptr : lg + (size_t)(i + 1) * H_,
            last ? nullptr : rg + (size_t)(i + 1) * H_,
            0, last ? -1 : 2, 0, oall, olast);
    }
}

// round 9
// speedup vs baseline: 1.1039x; 1.1039x over previous
#include <cuda_runtime.h>
#include <cuda_fp16.h>
#include <cstdint>

#define B_ 16
#define S_ 2048
#define H_ 512
#define W_ 4
#define L_ 2
#define SP_ (S_ + 2 * W_)   // 2056
#define BS_ (B_ * S_)       // 32768

// ---------------------------------------------------------------------------
// Scratch (__device__ globals; allocation-free rule)
// ---------------------------------------------------------------------------
__device__ __align__(256) __half g_pad_h[B_ * SP_ * H_];     // fp16 padded input
__device__ __align__(256) float  g_lo[BS_ * H_];             // fp32 residual L
__device__ __align__(256) float  g_ro[BS_ * H_];             // fp32 residual R
__device__ __align__(256) __half g_u[2 * BS_ * H_];          // fp16 x*gamma (GEMM1 A), per side
__device__ __align__(256) __half g_h[2 * BS_ * H_];          // fp16 hidden (GEMM2 A), per side
__device__ __align__(256) float  g_stats[4 * BS_ * 2];       // (sum, sumsq) x 4 phases
__device__ __align__(256) float  g_q[4 * H_];                // gamma @ W1 per (layer,side)
__device__ __align__(256) float  g_p[4 * H_];                // beta @ W1 + b1
// fp16 weights, layout matches f2h_all linear order:
#define OFF_WL  0
#define OFF_WR  1048576
#define OFF_LW1 2097152
#define OFF_LW2 2621440
#define OFF_RW1 3145728
#define OFF_RW2 3670016
__device__ __align__(256) __half g_wh[4194304];

// ---------------------------------------------------------------------------
// PTX helpers
// ---------------------------------------------------------------------------
__device__ __forceinline__ uint32_t smem_u32(const void* p) {
    uint32_t a;
    asm("{ .reg .u64 t; cvta.to.shared.u64 t, %1; cvt.u32.u64 %0, t; }" : "=r"(a) : "l"(p));
    return a;
}
__device__ __forceinline__ void cp_async16(uint32_t dst, const void* src) {
    asm volatile("cp.async.cg.shared.global [%0], [%1], 16;" :: "r"(dst), "l"(src) : "memory");
}
template <int N>
__device__ __forceinline__ void cp_wait() {
    asm volatile("cp.async.wait_group %0;" :: "n"(N) : "memory");
}
#define CP_COMMIT() asm volatile("cp.async.commit_group;" ::: "memory")

__device__ __forceinline__ void ldm_x4(uint32_t r[4], uint32_t addr) {
    asm volatile("ldmatrix.sync.aligned.m8n8.x4.shared.b16 {%0,%1,%2,%3}, [%4];"
        : "=r"(r[0]), "=r"(r[1]), "=r"(r[2]), "=r"(r[3]) : "r"(addr));
}
__device__ __forceinline__ void ldm_x4_t(uint32_t r[4], uint32_t addr) {
    asm volatile("ldmatrix.sync.aligned.m8n8.x4.trans.shared.b16 {%0,%1,%2,%3}, [%4];"
        : "=r"(r[0]), "=r"(r[1]), "=r"(r[2]), "=r"(r[3]) : "r"(addr));
}
__device__ __forceinline__ void mma_f16(float c[4], const uint32_t a[4],
                                        uint32_t b0, uint32_t b1) {
    asm volatile(
        "mma.sync.aligned.m16n8k16.row.col.f32.f16.f16.f32 "
        "{%0,%1,%2,%3}, {%4,%5,%6,%7}, {%8,%9}, {%0,%1,%2,%3};"
        : "+f"(c[0]), "+f"(c[1]), "+f"(c[2]), "+f"(c[3])
        : "r"(a[0]), "r"(a[1]), "r"(a[2]), "r"(a[3]), "r"(b0), "r"(b1));
}

// ---------------------------------------------------------------------------
// Single kernel: convert ALL fp32 weights -> fp16 into g_wh (linear layout)
// ---------------------------------------------------------------------------
__global__ void f2h_all(const float* __restrict__ Wl, const float* __restrict__ Wr,
                        const float* __restrict__ lw1, const float* __restrict__ lw2,
                        const float* __restrict__ rw1, const float* __restrict__ rw2) {
    int i = blockIdx.x * blockDim.x + threadIdx.x;   // uint4 index (8 halves)
    if (i >= 524288) return;
    const float* src;
    int off;
    if (i < 131072)      { src = Wl;  off = i; }
    else if (i < 262144) { src = Wr;  off = i - 131072; }
    else if (i < 327680) { src = lw1; off = i - 262144; }
    else if (i < 393216) { src = lw2; off = i - 327680; }
    else if (i < 458752) { src = rw1; off = i - 393216; }
    else                 { src = rw2; off = i - 458752; }
    float4 v0 = ((const float4*)src)[2 * off];
    float4 v1 = ((const float4*)src)[2 * off + 1];
    __half2 h[4];
    h[0] = __floats2half2_rn(v0.x, v0.y);
    h[1] = __floats2half2_rn(v0.z, v0.w);
    h[2] = __floats2half2_rn(v1.x, v1.y);
    h[3] = __floats2half2_rn(v1.z, v1.w);
    ((uint4*)g_wh)[i] = *(uint4*)h;
}

// ---------------------------------------------------------------------------
// prep: q = gamma @ W1, p = beta @ W1 + b1, per combo = layer*2 + side
// ---------------------------------------------------------------------------
__global__ void prep_qp(const float* __restrict__ lw1, const float* __restrict__ rw1,
                        const float* __restrict__ lg, const float* __restrict__ lbeta,
                        const float* __restrict__ lb1,
                        const float* __restrict__ rg, const float* __restrict__ rbeta,
                        const float* __restrict__ rb1) {
    int combo = blockIdx.y;
    int layer = combo >> 1, side = combo & 1;
    const float* Wm = (side ? rw1 : lw1) + (size_t)layer * H_ * H_;
    const float* ga = (side ? rg : lg) + layer * H_;
    const float* be = (side ? rbeta : lbeta) + layer * H_;
    const float* b1 = (side ? rb1 : lb1) + layer * H_;
    int j = blockIdx.x * 128 + threadIdx.x;
    float q = 0.f, p = 0.f;
    for (int k = 0; k < H_; k++) {
        float w = Wm[(size_t)k * H_ + j];
        q += ga[k] * w;
        p += be[k] * w;
    }
    g_q[combo * H_ + j] = q;
    g_p[combo * H_ + j] = p + b1[j];
}

// ---------------------------------------------------------------------------
// pad: [left ; inputs ; right] -> g_pad_h (fp16)
// ---------------------------------------------------------------------------
__global__ void pad_kernel(const float* __restrict__ inp,
                           const float* __restrict__ lp,
                           const float* __restrict__ rp) {
    const int H4 = H_ / 4;
    int idx = blockIdx.x * blockDim.x + threadIdx.x;
    if (idx >= B_ * SP_ * H4) return;
    int h4 = idx % H4;
    int t = idx / H4;
    int p = t % SP_;
    int b = t / SP_;
    float4 v;
    if (p < W_) v = ((const float4*)lp)[p * H4 + h4];
    else if (p < W_ + S_) v = ((const float4*)inp)[((size_t)b * S_ + (p - W_)) * H4 + h4];
    else v = ((const float4*)rp)[(p - W_ - S_) * H4 + h4];
    __half2 h[2];
    h[0] = __floats2half2_rn(v.x, v.y);
    h[1] = __floats2half2_rn(v.z, v.w);
    ((uint2*)g_pad_h)[idx] = *(uint2*)h;
}

// ---------------------------------------------------------------------------
// fp16 mma.sync GEMM: 128x128 CTA tile, BK=32, 4-stage cp.async,
// single __syncthreads per chunk. Warp layout by NT:
//   NT=128: 4 warps 2x2, warp tile 64x64 (min smem redundancy; long-K MODE0)
//   NT=256: 8 warps 2x4, warp tile 64x32 (max latency hiding; short-K layers)
// MODE 0 (grid 4,16,32): wide proj. relu(acc+b) -> X fp32, u, stats.
// MODE 1 (grid 4,256,2): A = g_u. v = rstd*acc - rstd*mu*q + p, relu -> g_h.
// MODE 2 (grid 4,256,2): A = g_h. v = X + acc + b2 -> out_all (+out_last)
//        at col side*H_. If not last: X = v, u, stats.
// ---------------------------------------------------------------------------
constexpr int A_STAGE_B = 128 * 80;
constexpr int B_STAGE_B = 32 * 272;
constexpr int STAGE_B = A_STAGE_B + B_STAGE_B;  // 18944 B
constexpr int STAGES = 4;
constexpr int SMEM_BYTES = STAGES * STAGE_B;    // 75776 B (2 CTAs/SM)

template <int MODE, int KT, int NT>
__global__ void __launch_bounds__(NT, 2)
tc_gemm(int woffL, int woffR,
        const float* __restrict__ bL, const float* __restrict__ bR,
        const float* __restrict__ gamL, const float* __restrict__ gamR,
        int qp_base, int statsPhase, int ln_phase,
        float* __restrict__ outA, float* __restrict__ outL) {
    constexpr int WNC = NT / 64;          // warps in N: 2 or 4
    constexpr int TNW = 128 / WNC;        // warp tile N: 64 or 32
    constexpr int NP = TNW / 16;          // trans-ldmatrix groups: 4 or 2
    constexpr int NR = 2 * NP;            // 8-col accum groups: 8 or 4
    constexpr int LS = 512 / NT;          // loadStage chunk iters: 4 or 2

    extern __shared__ char smraw[];
    const uint32_t sbase = smem_u32(smraw);
    const int tid = threadIdx.x;
    const int lane = tid & 31, wid = tid >> 5;
    const int warpM = wid / WNC, warpN = wid % WNC;
    const int gid = lane >> 2, t4 = lane & 3;
    const int lane15 = lane & 15, laneHi = lane >> 4;
    const int n0 = blockIdx.x * 128;

    int side;
    size_t m0;
    const __half* A;
    if (MODE == 0) {
        side = blockIdx.z >> 4;
        int bb = blockIdx.z & 15;
        m0 = (size_t)bb * S_ + blockIdx.y * 128;
        A = g_pad_h + ((size_t)bb * SP_ + blockIdx.y * 128 + side * (W_ + 1)) * H_;
    } else {
        side = blockIdx.z;
        m0 = (size_t)blockIdx.y * 128;
        A = (MODE == 1 ? g_u : g_h) + ((size_t)side * BS_ + m0) * H_;
    }
    const __half* Wm = g_wh + (side ? woffR : woffL);
    float* X = side ? g_ro : g_lo;
    const float* bias = side ? bR : bL;
    const float* gam = side ? gamR : gamL;

    float c[4][NR][4];
#pragma unroll
    for (int i = 0; i < 4; i++)
#pragma unroll
        for (int j = 0; j < NR; j++)
#pragma unroll
            for (int q = 0; q < 4; q++) c[i][j][q] = 0.f;

    auto loadStage = [&](int kt, int s) {
        const int k0 = kt * 32;
        uint32_t base = sbase + (uint32_t)s * STAGE_B;
#pragma unroll
        for (int i = 0; i < LS; i++) {
            int ch = tid + i * NT;
            int ar = ch >> 2, ac = ch & 3;
            cp_async16(base + ar * 80 + ac * 16, A + (size_t)ar * H_ + k0 + ac * 8);
            int br = ch >> 4, bc = ch & 15;
            cp_async16(base + A_STAGE_B + br * 272 + bc * 16,
                       Wm + (size_t)(k0 + br) * H_ + n0 + bc * 8);
        }
        CP_COMMIT();
    };

    loadStage(0, 0);
    if (KT > 1) loadStage(1, 1);
    if (KT > 2) loadStage(2, 2);

    for (int kt = 0; kt < KT; kt++) {
        int rem = KT - 1 - kt;
        if (rem >= 2) cp_wait<2>();
        else if (rem == 1) cp_wait<1>();
        else cp_wait<0>();
        __syncthreads();
        if (kt + 3 < KT) loadStage(kt + 3, (kt + 3) % STAGES);

        const uint32_t a_base = sbase + (uint32_t)((kt % STAGES) * STAGE_B);
        const uint32_t b_base = a_base + A_STAGE_B;
#pragma unroll
        for (int ks = 0; ks < 2; ks++) {
            uint32_t a[4][4], bb2[NP][4];
#pragma unroll
            for (int mr = 0; mr < 4; mr++)
                ldm_x4(a[mr], a_base + (warpM * 64 + mr * 16 + lane15) * 80
                                 + ks * 32 + laneHi * 16);
#pragma unroll
            for (int np = 0; np < NP; np++)
                ldm_x4_t(bb2[np], b_base + (ks * 16 + lane15) * 272
                                    + (warpN * TNW + np * 16 + laneHi * 8) * 2);
#pragma unroll
            for (int mr = 0; mr < 4; mr++)
#pragma unroll
                for (int np = 0; np < NP; np++) {
                    mma_f16(c[mr][2 * np + 0], a[mr], bb2[np][0], bb2[np][1]);
                    mma_f16(c[mr][2 * np + 1], a[mr], bb2[np][2], bb2[np][3]);
                }
        }
    }

    // ---------------- epilogue ----------------
    const int colbase = n0 + warpN * TNW + t4 * 2;
    __half* uSide = g_u + (size_t)side * BS_ * H_;

    if (MODE == 1) {
        const int cb = (qp_base + side) * H_;
        const float* stats = g_stats + (size_t)(ln_phase + side) * BS_ * 2;
        __half* hSide = g_h + (size_t)side * BS_ * H_;
#pragma unroll
        for (int mr = 0; mr < 4; mr++) {
#pragma unroll
            for (int hh = 0; hh < 2; hh++) {
                size_t r = m0 + warpM * 64 + mr * 16 + gid + hh * 8;
                float2 st = *(const float2*)(stats + r * 2);
                float mu = st.x * (1.0f / H_);
                float var = st.y * (1.0f / H_) - mu * mu;
                float rstd = rsqrtf(fmaxf(var, 0.f) + 1e-5f);
                float mt = -rstd * mu;
                __half* hrow = hSide + r * H_;
#pragma unroll
                for (int nr = 0; nr < NR; nr++) {
                    int col = colbase + nr * 8;
                    float2 q2 = *(const float2*)(g_q + cb + col);
                    float2 p2 = *(const float2*)(g_p + cb + col);
                    float v0 = fmaf(rstd, c[mr][nr][hh * 2 + 0], fmaf(mt, q2.x, p2.x));
                    float v1 = fmaf(rstd, c[mr][nr][hh * 2 + 1], fmaf(mt, q2.y, p2.y));
                    *(__half2*)(hrow + col) =
                        __floats2half2_rn(fmaxf(v0, 0.f), fmaxf(v1, 0.f));
                }
            }
        }
        return;
    }

    // MODE 0 / MODE 2
    float* statsDst = (statsPhase >= 0)
        ? g_stats + (size_t)(statsPhase + side) * BS_ * 2 : (float*)0;
    const int outcol0 = colbase + side * H_;   // concat offset in [.,.,2H] outputs

#pragma unroll
    for (int mr = 0; mr < 4; mr++) {
#pragma unroll
        for (int hh = 0; hh < 2; hh++) {
            size_t r = m0 + warpM * 64 + mr * 16 + gid + hh * 8;
            float* xrow = X + r * H_;
            float s = 0.f, sq = 0.f;
#pragma unroll
            for (int nr = 0; nr < NR; nr++) {
                int col = colbase + nr * 8;
                float2 bv = *(const float2*)(bias + col);
                float v0 = c[mr][nr][hh * 2 + 0] + bv.x;
                float v1 = c[mr][nr][hh * 2 + 1] + bv.y;
                if (MODE == 0) {
                    v0 = fmaxf(v0, 0.f);
                    v1 = fmaxf(v1, 0.f);
                    *(float2*)(xrow + col) = make_float2(v0, v1);
                } else {
                    float2 rv = *(const float2*)(xrow + col);
                    v0 += rv.x;
                    v1 += rv.y;
                    size_t bi = r >> 11, si = r & 2047;
                    int ocol = outcol0 + nr * 8;
                    *(float2*)(outA + (si * B_ + bi) * (size_t)(2 * H_) + ocol) =
                        make_float2(v0, v1);
                    if (outL)
                        *(float2*)(outL + (bi * S_ + si) * (size_t)(2 * H_) + ocol) =
                            make_float2(v0, v1);
                    if (statsPhase >= 0) *(float2*)(xrow + col) = make_float2(v0, v1);
                }
                if (MODE == 0 || statsPhase >= 0) {
                    float2 gv = *(const float2*)(gam + col);
                    *(__half2*)(uSide + r * H_ + col) =
                        __floats2half2_rn(v0 * gv.x, v1 * gv.y);
                    s += v0 + v1;
                    sq += v0 * v0 + v1 * v1;
                }
            }
            if (statsDst) {
                s += __shfl_xor_sync(0xffffffffu, s, 1);
                sq += __shfl_xor_sync(0xffffffffu, sq, 1);
                s += __shfl_xor_sync(0xffffffffu, s, 2);
                sq += __shfl_xor_sync(0xffffffffu, sq, 2);
                if (t4 == 0) {
                    atomicAdd(statsDst + r * 2, s);
                    atomicAdd(statsDst + r * 2 + 1, sq);
                }
            }
        }
    }
}

// ---------------------------------------------------------------------------
extern "C" void kernel_launch(void* const* d_in, const int* in_sizes, int n_in,
                              void* d_out, int out_size) {
    const float* inputs = (const float*)d_in[0];
    const float* lp     = (const float*)d_in[1];
    const float* rp     = (const float*)d_in[2];
    const float* Wl     = (const float*)d_in[3];
    const float* bl     = (const float*)d_in[4];
    const float* Wr     = (const float*)d_in[5];
    const float* br     = (const float*)d_in[6];
    const float* lw1    = (const float*)d_in[7];
    const float* lb1    = (const float*)d_in[8];
    const float* lw2    = (const float*)d_in[9];
    const float* lb2    = (const float*)d_in[10];
    const float* lg     = (const float*)d_in[11];
    const float* lbeta  = (const float*)d_in[12];
    const float* rw1    = (const float*)d_in[13];
    const float* rb1    = (const float*)d_in[14];
    const float* rw2    = (const float*)d_in[15];
    const float* rb2    = (const float*)d_in[16];
    const float* rg     = (const float*)d_in[17];
    const float* rbeta  = (const float*)d_in[18];
    float* out = (float*)d_out;
    (void)in_sizes; (void)n_in; (void)out_size;

    cudaFuncSetAttribute(tc_gemm<0, 64, 128>,
                         cudaFuncAttributeMaxDynamicSharedMemorySize, SMEM_BYTES);
    cudaFuncSetAttribute(tc_gemm<1, 16, 256>,
                         cudaFuncAttributeMaxDynamicSharedMemorySize, SMEM_BYTES);
    cudaFuncSetAttribute(tc_gemm<2, 16, 256>,
                         cudaFuncAttributeMaxDynamicSharedMemorySize, SMEM_BYTES);

    // 0) zero stats
    float* statsPtr;
    cudaGetSymbolAddress((void**)&statsPtr, g_stats);
    cudaMemsetAsync(statsPtr, 0, 4 * BS_ * 2 * sizeof(float));

    // 1) pad + weight convert + LN-fold precompute
    int padTotal = B_ * SP_ * (H_ / 4);
    pad_kernel<<<(padTotal + 255) / 256, 256>>>(inputs, lp, rp);
    f2h_all<<<2048, 256>>>(Wl, Wr, lw1, lw2, rw1, rw2);
    prep_qp<<<dim3(4, 4), 128>>>(lw1, rw1, lg, lbeta, lb1, rg, rbeta, rb1);

    // 2) wide projections, L+R merged (128 threads, 64x64 warp tiles)
    tc_gemm<0, 64, 128><<<dim3(4, 16, 32), 128, SMEM_BYTES>>>(
        OFF_WL, OFF_WR, bl, br, lg, rg, 0, 0, 0, nullptr, nullptr);

    // 3) residual FF layers, L+R merged (256 threads, 64x32 warp tiles)
    for (int i = 0; i < L_; i++) {
        bool last = (i == L_ - 1);
        tc_gemm<1, 16, 256><<<dim3(4, 256, 2), 256, SMEM_BYTES>>>(
            OFF_LW1 + i * 262144, OFF_RW1 + i * 262144,
            nullptr, nullptr, nullptr, nullptr,
            i * 2, -1, (i == 0) ? 0 : 2, nullptr, nullptr);

        float* oall = out + (size_t)i * S_ * B_ * 2 * H_;
        float* olast = last ? out + (size_t)L_ * S_ * B_ * 2 * H_ : nullptr;
        tc_gemm<2, 16, 256><<<dim3(4, 256, 2), 256, SMEM_BYTES>>>(
            OFF_LW2 + i * 262144, OFF_RW2 + i * 262144,
            lb2 + (size_t)i * H_, rb2 + (size_t)i * H_,
            last ? nullptr : lg + (size_t)(i + 1) * H_,
            last ? nullptr : rg + (size_t)(i + 1) * H_,
            0, last ? -1 : 2, 0, oall, olast);
    }
}